// round 16
// baseline (speedup 1.0000x reference)
#include <cuda_runtime.h>
#include <cuda_fp16.h>
#include <math.h>

#define BB 64
#define LL 4096
#define NV 128
#define FF 2049
#define MM 2048
#define NROWS (BB*NV)   // 8192
#define NG 8            // n-groups for mag partials (16 rows each)
#define NC 33           // split-K chunks for gemm1 (64 k each)

// pad every 8 elements: conflict-free exchanges for the radix-8 Stockham
#define PD8(i) ((i) + ((i) >> 3))
#define SH2 2304   // PD8(2047)=2302

// ---------------- device scratch (static, no allocation) ----------------
static __device__ __half  d_xT[(size_t)NROWS * LL];     // 64MB: xT (fp16), later reused as rec
static __device__ __half2 d_Zh[(size_t)NROWS * MM];     // 64MB packed fwd FFT, fp16 (re,im)
static __device__ float   d_mean[NROWS];
static __device__ float   d_sv[NROWS];
static __device__ float   d_mag[BB * FF];
static __device__ float   d_magp[(size_t)NG * BB * FF]; // unnormalized mag partials
static __device__ float   d_hpart[(size_t)NC * BB * FF];
static __device__ float   d_wmask[BB * FF];
static __device__ int     d_bandof[FF];
static __device__ float2  d_twf[2048];                  // e^{-2pi i j/2048}, full period
static __device__ float2  d_tw4096[1025];               // e^{-2pi i k/4096}

__device__ __forceinline__ float2 cmulf(float2 a, float2 b) {
    return make_float2(a.x*b.x - a.y*b.y, a.x*b.y + a.y*b.x);
}
__device__ __forceinline__ float2 cadd(float2 a, float2 b){ return make_float2(a.x+b.x, a.y+b.y); }
__device__ __forceinline__ float2 csub(float2 a, float2 b){ return make_float2(a.x-b.x, a.y-b.y); }
// SIGN<0: -i*d ; SIGN>0: +i*d
template<int SIGN> __device__ __forceinline__ float2 crot(float2 d){
    return (SIGN < 0) ? make_float2(d.y, -d.x) : make_float2(-d.y, d.x);
}

template<int SIGN> __device__ __forceinline__ void bfly4(float2 v[4]){
    float2 p = cadd(v[0], v[2]), q = csub(v[0], v[2]);
    float2 s = cadd(v[1], v[3]), d = csub(v[1], v[3]);
    float2 rd = crot<SIGN>(d);
    v[0] = cadd(p, s); v[2] = csub(p, s);
    v[1] = cadd(q, rd); v[3] = csub(q, rd);
}

template<int SIGN> __device__ __forceinline__ void bfly8(float2 v[8]){
    const float C = 0.70710678118654752f;
    float2 a0 = cadd(v[0], v[4]), b0 = csub(v[0], v[4]);
    float2 a1 = cadd(v[1], v[5]), b1 = csub(v[1], v[5]);
    float2 a2 = cadd(v[2], v[6]), b2 = csub(v[2], v[6]);
    float2 a3 = cadd(v[3], v[7]), b3 = csub(v[3], v[7]);
    // odd-part twiddles: w^1, w^2, w^3 with w = e^{SIGN*2pi i/8}
    float2 c1 = (SIGN < 0) ? make_float2(C*(b1.x + b1.y), C*(b1.y - b1.x))
                           : make_float2(C*(b1.x - b1.y), C*(b1.y + b1.x));
    float2 c2 = crot<SIGN>(b2);
    float2 c3 = (SIGN < 0) ? make_float2(C*(b3.y - b3.x), -C*(b3.x + b3.y))
                           : make_float2(-C*(b3.x + b3.y), C*(b3.x - b3.y));
    float2 e[4] = {a0, a1, a2, a3};  bfly4<SIGN>(e);
    float2 o[4] = {b0, c1, c2, c3};  bfly4<SIGN>(o);
    v[0]=e[0]; v[2]=e[1]; v[4]=e[2]; v[6]=e[3];
    v[1]=o[0]; v[3]=o[1]; v[5]=o[2]; v[7]=o[3];
}

__device__ __forceinline__ void twchain8(float2 v[8], float2 w1){
    float2 w = w1;
    v[1] = cmulf(v[1], w);
    #pragma unroll
    for (int r = 2; r < 8; r++) { w = cmulf(w, w1); v[r] = cmulf(v[r], w); }
}

__device__ __forceinline__ __half2 pack_h2(float2 a){ return __floats2half2_rn(a.x, a.y); }
__device__ __forceinline__ float2  unpk_h2(__half2 h){ return __half22float2(h); }

// 3 radix-8 Stockham passes (P=1,8,64), ping-pong HA->HB->HA through fp16
// shared (butterfly math stays fp32 in registers). Only 3 barriers.
// Result (sub-length-512 state) is left in HA; caller runs the final radix-4
// (P=512) pass fused with the global store.
template<int SIGN>
__device__ __forceinline__ void fft3pass(float2 v[8], __half2* HA, __half2* HB, int t){
    // pass 1: P=1 (no twiddle), out[8t + r] -> HA
    bfly8<SIGN>(v);
    #pragma unroll
    for (int r = 0; r < 8; r++) HA[PD8(8*t + r)] = pack_h2(v[r]);
    __syncthreads();
    // pass 2: P=8, HA -> HB
    #pragma unroll
    for (int r = 0; r < 8; r++) v[r] = unpk_h2(HA[PD8(t + 256*r)]);
    {
        int k = t & 7;
        float2 w1 = d_twf[k * 32]; if (SIGN > 0) w1.y = -w1.y;
        twchain8(v, w1);
        bfly8<SIGN>(v);
        int base = 8*(t - k) + k;
        #pragma unroll
        for (int r = 0; r < 8; r++) HB[PD8(base + 8*r)] = pack_h2(v[r]);
    }
    __syncthreads();
    // pass 3: P=64, HB -> HA
    #pragma unroll
    for (int r = 0; r < 8; r++) v[r] = unpk_h2(HB[PD8(t + 256*r)]);
    {
        int k = t & 63;
        float2 w1 = d_twf[k * 4]; if (SIGN > 0) w1.y = -w1.y;
        twchain8(v, w1);
        bfly8<SIGN>(v);
        int base = 8*(t - k) + k;
        #pragma unroll
        for (int r = 0; r < 8; r++) HA[PD8(base + 64*r)] = pack_h2(v[r]);
    }
    __syncthreads();
}

// ---------------- init: twiddles + band boundaries (one kernel) ----------------
__global__ void k_init(const float* __restrict__ bb) {
    int i = blockIdx.x * blockDim.x + threadIdx.x;
    if (i < 2048) {
        float s, c; sincospif(-(float)i / 1024.0f, &s, &c);
        d_twf[i] = make_float2(c, s);
    }
    if (i < 1025) {
        float s, c; sincospif(-(float)i / 2048.0f, &s, &c);
        d_tw4096[i] = make_float2(c, s);
    }
    if (blockIdx.x == 1 && threadIdx.x == 1023) {   // one thread, parallel with twiddle fill
        float s[7];
        for (int q = 0; q < 7; q++) s[q] = bb[q];
        for (int q = 1; q < 7; q++) {
            float v = s[q]; int j = q - 1;
            while (j >= 0 && s[j] > v) { s[j+1] = s[j]; j--; }
            s[j+1] = v;
        }
        float b01[9];
        b01[0] = 0.0f;
        for (int q = 0; q < 7; q++) b01[q+1] = 1.0f / (1.0f + expf(-s[q]));
        b01[8] = 1.0f;
        int idx[9];
        for (int q = 0; q < 9; q++) {
            int v = (int)(b01[q] * (float)FF);
            if (v < 0) v = 0; if (v > FF) v = FF;
            idx[q] = v;
        }
        idx[8] = FF;
        for (int e = 0; e < 8; e++)
            for (int f = idx[e]; f < idx[e+1]; f++) d_bandof[f] = e;
    }
}

// ---------------- transpose x[B,L,N] (fp32) -> xT[B,N,L] (fp16) ----------------
// tile: 64 l x 32 n. Loads 128B/warp fp32; stores 128B/warp half2.
__global__ __launch_bounds__(256) void k_transpose(const float* __restrict__ x) {
    __shared__ float tile[64][33];
    int b = blockIdx.z;
    int l0 = blockIdx.x * 64, n0 = blockIdx.y * 32;
    int tx = threadIdx.x, ty = threadIdx.y;
    #pragma unroll
    for (int r = 0; r < 8; r++) {
        int lr = ty + 8*r;
        tile[lr][tx] = x[((size_t)b*LL + (l0+lr)) * NV + n0 + tx];
    }
    __syncthreads();
    __half2* xo = (__half2*)d_xT;
    #pragma unroll
    for (int r = 0; r < 4; r++) {
        int nr = ty + 8*r;
        size_t o = ((size_t)b*NV + (n0+nr)) * (LL/2) + (l0/2) + tx;
        xo[o] = __floats2half2_rn(tile[2*tx][nr], tile[2*tx+1][nr]);
    }
}

// ---------------- forward FFT + row stats; store packed Z as fp16 ----------------
__global__ __launch_bounds__(256, 6) void k_fft_fwd() {
    __shared__ __half2 HA[SH2], HB[SH2];
    __shared__ float red[16];
    int t = threadIdx.x, row = blockIdx.x;
    int lane = t & 31, warp = t >> 5;
    const __half2* xr = (const __half2*)(d_xT + (size_t)row * LL);
    float2 v[8];
    float s1 = 0.f, s2 = 0.f;
    #pragma unroll
    for (int q = 0; q < 8; q++) {
        float2 z = __half22float2(xr[t + 256*q]);   // (x[2m], x[2m+1]) packing for free
        v[q] = z;
        s1 += z.x + z.y;
        s2 += z.x*z.x + z.y*z.y;
    }
    #pragma unroll
    for (int o = 16; o > 0; o >>= 1) {
        s1 += __shfl_xor_sync(0xffffffffu, s1, o);
        s2 += __shfl_xor_sync(0xffffffffu, s2, o);
    }
    if (lane == 0) { red[warp] = s1; red[warp + 8] = s2; }
    __syncthreads();
    if (t == 0) {
        float t1 = 0.f, t2 = 0.f;
        #pragma unroll
        for (int w = 0; w < 8; w++) { t1 += red[w]; t2 += red[w + 8]; }
        float mean = t1 * (1.0f / LL);
        float var  = t2 * (1.0f / LL) - mean*mean + 1e-6f;
        d_mean[row] = mean;
        d_sv[row]   = sqrtf(var);
    }
    // no extra sync needed: fft3pass writes HA/HB (disjoint from red); its first barrier covers it
    fft3pass<-1>(v, HA, HB, t);
    // final radix-4 pass (P=512) fused with fp16 global store
    __half2* Zr = d_Zh + (size_t)row * MM;
    #pragma unroll
    for (int h = 0; h < 2; h++) {
        int jj = t + 256*h;
        float2 u[4];
        #pragma unroll
        for (int m = 0; m < 4; m++) u[m] = unpk_h2(HA[PD8(jj + 512*m)]);
        float2 w1 = d_twf[jj];
        float2 w = w1;
        u[1] = cmulf(u[1], w); w = cmulf(w, w1); u[2] = cmulf(u[2], w); w = cmulf(w, w1); u[3] = cmulf(u[3], w);
        bfly4<-1>(u);
        #pragma unroll
        for (int m = 0; m < 4; m++)
            Zr[jj + 512*m] = pack_h2(u[m]);
    }
}

// ---------------- magp[g][b][f] = sum over 16-row n-group of |X[b,n,f]| ----------------
// four interleaved accumulator chains to quadruple memory-level parallelism
__global__ __launch_bounds__(128) void k_mag() {
    int b = blockIdx.y;
    int g = blockIdx.z;
    int k = blockIdx.x * 128 + threadIdx.x;
    if (k > 1024) return;
    const __half2* Zb = d_Zh + (size_t)b * NV * MM + (size_t)(g * 16) * MM;
    float2 W = d_tw4096[k];
    float a1[4] = {0.f, 0.f, 0.f, 0.f};
    float a2[4] = {0.f, 0.f, 0.f, 0.f};
    if (k == 0) {
        #pragma unroll
        for (int n = 0; n < 16; n += 4) {
            #pragma unroll
            for (int q = 0; q < 4; q++) {
                float2 z = __half22float2(Zb[(size_t)(n+q) * MM]);
                a1[q] += fabsf(z.x + z.y);
                a2[q] += fabsf(z.x - z.y);
            }
        }
    } else if (k == 1024) {
        #pragma unroll
        for (int n = 0; n < 16; n += 4) {
            #pragma unroll
            for (int q = 0; q < 4; q++) {
                float2 z = __half22float2(Zb[(size_t)(n+q) * MM + 1024]);
                a1[q] += sqrtf(z.x*z.x + z.y*z.y);
            }
        }
    } else {
        #pragma unroll 2
        for (int n = 0; n < 16; n += 4) {
            float2 zk[4], zm[4];
            #pragma unroll
            for (int q = 0; q < 4; q++) {
                const __half2* Zr = Zb + (size_t)(n+q) * MM;
                zk[q] = __half22float2(Zr[k]);
                zm[q] = __half22float2(Zr[MM - k]);
            }
            #pragma unroll
            for (int q = 0; q < 4; q++) {
                float2 Xe = make_float2(0.5f*(zk[q].x + zm[q].x), 0.5f*(zk[q].y - zm[q].y));
                float2 T  = make_float2(zk[q].x - zm[q].x, zk[q].y + zm[q].y);
                float2 Xo = make_float2(0.5f*T.y, -0.5f*T.x);
                float2 WX = cmulf(W, Xo);
                float2 Xk = make_float2(Xe.x + WX.x, Xe.y + WX.y);
                float2 Xm = make_float2(Xe.x - WX.x, Xe.y - WX.y);  // |conj| == | |
                a1[q] += sqrtf(Xk.x*Xk.x + Xk.y*Xk.y);
                a2[q] += sqrtf(Xm.x*Xm.x + Xm.y*Xm.y);
            }
        }
    }
    float s1 = (a1[0] + a1[1]) + (a1[2] + a1[3]);
    float s2 = (a2[0] + a2[1]) + (a2[2] + a2[3]);
    float* mp = d_magp + (size_t)g * BB * FF + b*FF;
    mp[k] = s1;
    if (k == 0)          mp[2048]   = s2;
    else if (k < 1024)   mp[MM - k] = s2;
}

// ---------------- mag[b][f] = (sum_g magp[g][b][f]) / NV ----------------
__global__ __launch_bounds__(256) void k_magred() {
    int idx = blockIdx.x * 256 + threadIdx.x;
    if (idx >= BB * FF) return;
    float s = 0.f;
    #pragma unroll
    for (int g = 0; g < NG; g++) s += d_magp[(size_t)g * BB * FF + idx];
    d_mag[idx] = s * (1.0f / NV);
}

// ---------------- GEMM1 split-K partials: hpart[c] = mag @ W1 (k chunk c, 64 wide) ----------------
__global__ __launch_bounds__(256) void k_gemm1(const float* __restrict__ W1) {
    __shared__ float Smag[16][65];   // [kk][b]
    __shared__ float Sw[16][33];     // [kk][j]
    int j0 = blockIdx.x * 32;
    int k0 = blockIdx.y * 64;
    int t = threadIdx.x;
    int bq = t >> 4;
    int jq = t & 15;
    float acc[4][2];
    #pragma unroll
    for (int i = 0; i < 4; i++) { acc[i][0] = 0.f; acc[i][1] = 0.f; }

    for (int ks = 0; ks < 64; ks += 16) {
        #pragma unroll
        for (int q = 0; q < 4; q++) {
            int e = t + 256*q;
            int bb2 = e >> 4, kk = e & 15;
            int kg = k0 + ks + kk;
            Smag[kk][bb2] = (kg < FF) ? d_mag[bb2*FF + kg] : 0.f;
        }
        #pragma unroll
        for (int q = 0; q < 2; q++) {
            int e = t + 256*q;
            int kk = e >> 5, j = e & 31;
            int kg = k0 + ks + kk, jg = j0 + j;
            Sw[kk][j] = (kg < FF && jg < FF) ? W1[(size_t)kg*FF + jg] : 0.f;
        }
        __syncthreads();
        #pragma unroll
        for (int kk = 0; kk < 16; kk++) {
            float m0 = Smag[kk][bq*4+0], m1 = Smag[kk][bq*4+1];
            float m2 = Smag[kk][bq*4+2], m3 = Smag[kk][bq*4+3];
            float w0 = Sw[kk][jq*2+0],   w1v = Sw[kk][jq*2+1];
            acc[0][0] += m0*w0; acc[0][1] += m0*w1v;
            acc[1][0] += m1*w0; acc[1][1] += m1*w1v;
            acc[2][0] += m2*w0; acc[2][1] += m2*w1v;
            acc[3][0] += m3*w0; acc[3][1] += m3*w1v;
        }
        __syncthreads();
    }
    float* hp = d_hpart + (size_t)blockIdx.y * BB * FF;
    #pragma unroll
    for (int i = 0; i < 4; i++) {
        int bb2 = bq*4 + i;
        #pragma unroll
        for (int jj = 0; jj < 2; jj++) {
            int jg = j0 + jq*2 + jj;
            if (jg < FF) hp[bb2*FF + jg] = acc[i][jj];
        }
    }
}

// ---------------- GEMM2 (+split-K reduce + bias + relu) + softmax + wmask ----------------
__global__ __launch_bounds__(256) void k_gate2(const float* __restrict__ W2,
                                               const float* __restrict__ b1,
                                               const float* __restrict__ b2) {
    __shared__ float sred[8][8];   // [warp][e]
    __shared__ float sw[8];
    int b = blockIdx.x, t = threadIdx.x;
    int warp = t >> 5, lane = t & 31;
    float acc[8];
    #pragma unroll
    for (int e = 0; e < 8; e++) acc[e] = 0.f;
    for (int k = t; k < FF; k += 256) {
        float hv = b1[k];
        #pragma unroll
        for (int c = 0; c < NC; c++) hv += d_hpart[(size_t)c * BB * FF + b*FF + k];
        hv = fmaxf(hv, 0.f);
        #pragma unroll
        for (int e = 0; e < 8; e++) acc[e] += hv * W2[k*8 + e];
    }
    #pragma unroll
    for (int e = 0; e < 8; e++)
        #pragma unroll
        for (int o = 16; o > 0; o >>= 1)
            acc[e] += __shfl_xor_sync(0xffffffffu, acc[e], o);
    if (lane == 0)
        #pragma unroll
        for (int e = 0; e < 8; e++) sred[warp][e] = acc[e];
    __syncthreads();
    if (t == 0) {
        float slog[8];
        for (int e = 0; e < 8; e++) {
            float s = b2[e];
            #pragma unroll
            for (int w = 0; w < 8; w++) s += sred[w][e];
            slog[e] = s;
        }
        float mx = slog[0];
        for (int e = 1; e < 8; e++) mx = fmaxf(mx, slog[e]);
        float den = 0.f, ex[8];
        for (int e = 0; e < 8; e++) { ex[e] = expf(slog[e] - mx); den += ex[e]; }
        for (int e = 0; e < 8; e++) sw[e] = ex[e] / den;
    }
    __syncthreads();
    for (int f = t; f < FF; f += 256)
        d_wmask[b*FF + f] = sw[d_bandof[f]];
}

// ---------------- inverse: masked unpack from fp16 Z (global), irfft, rescale; fp16 rec ----------------
__global__ __launch_bounds__(256, 6) void k_inv() {
    __shared__ __half2 HA[SH2], HB[SH2];
    int t = threadIdx.x, row = blockIdx.x;
    int b = row >> 7;               // row / NV
    const __half2* Zr = d_Zh + (size_t)row * MM;
    const float*   wm = d_wmask + b*FF;

    // masked Hermitian unpack straight from global fp16 Z into inverse pass-1 registers.
    // Both j and MM-j sides are contiguous per warp; the mirrored second touch is an L2 hit.
    float2 v[8];
    #pragma unroll
    for (int r = 0; r < 8; r++) {
        int j = t + 256*r;
        if (j == 0) {
            float2 z = __half22float2(Zr[0]);
            float Y0 = wm[0]    * (z.x + z.y);
            float Y2 = wm[2048] * (z.x - z.y);
            v[r] = make_float2(0.5f*(Y0 + Y2), 0.5f*(Y0 - Y2));
        } else if (j == 1024) {
            float m = wm[1024];
            float2 z = __half22float2(Zr[1024]);
            v[r] = make_float2(m*z.x, m*z.y);
        } else {
            int jl = (j < 1024) ? j : (2048 - j);
            float2 a  = __half22float2(Zr[jl]);
            float2 bz = __half22float2(Zr[2048 - jl]);
            float2 E  = make_float2(0.5f*(a.x + bz.x), 0.5f*(a.y - bz.y));
            float2 Tp = make_float2(a.x - bz.x, a.y + bz.y);
            float2 O  = make_float2(0.5f*Tp.y, -0.5f*Tp.x);
            float2 Wj = d_tw4096[jl];
            float2 T  = cmulf(Wj, O);
            float mj = wm[jl], mm2 = wm[2048 - jl];
            float p = 0.5f*(mj + mm2), qv = 0.5f*(mj - mm2);
            float2 Ep = make_float2(p*E.x + qv*T.x, p*E.y + qv*T.y);
            float2 Ot = make_float2(qv*E.x + p*T.x, qv*E.y + p*T.y);
            float2 Wc = make_float2(Wj.x, -Wj.y);
            float2 Op = cmulf(Wc, Ot);
            v[r] = (j < 1024) ? make_float2(Ep.x - Op.y,  Ep.y + Op.x)
                              : make_float2(Ep.x + Op.y, -Ep.y + Op.x);
        }
    }

    fft3pass<+1>(v, HA, HB, t);

    float sv = d_sv[row] * (1.0f / MM);
    float mean = d_mean[row];
    __half2* rec = (__half2*)(d_xT + (size_t)row * LL);
    #pragma unroll
    for (int h = 0; h < 2; h++) {
        int jj = t + 256*h;
        float2 u[4];
        #pragma unroll
        for (int m = 0; m < 4; m++) u[m] = unpk_h2(HA[PD8(jj + 512*m)]);
        float2 w1 = d_twf[jj]; w1.y = -w1.y;   // SIGN=+1
        float2 w = w1;
        u[1] = cmulf(u[1], w); w = cmulf(w, w1); u[2] = cmulf(u[2], w); w = cmulf(w, w1); u[3] = cmulf(u[3], w);
        bfly4<+1>(u);
        #pragma unroll
        for (int m = 0; m < 4; m++)
            rec[jj + 512*m] = __floats2half2_rn(u[m].x*sv + mean, u[m].y*sv + mean);
    }
}

// ---------------- out[b,l,n] = x[b,l,n] + rec[b,n,l] (rec fp16) ----------------
// tile: 64 l x 32 n. Loads 128B/warp half2; stores/loads 128B/warp fp32.
__global__ __launch_bounds__(256) void k_addT(const float* __restrict__ x,
                                              float* __restrict__ out) {
    __shared__ float tile[64][33];
    int b = blockIdx.z;
    int l0 = blockIdx.x * 64, n0 = blockIdx.y * 32;
    int tx = threadIdx.x, ty = threadIdx.y;
    const __half2* ri = (const __half2*)d_xT;
    #pragma unroll
    for (int r = 0; r < 4; r++) {
        int nr = ty + 8*r;
        size_t o = ((size_t)b*NV + (n0+nr)) * (LL/2) + (l0/2) + tx;
        float2 z = __half22float2(ri[o]);
        tile[2*tx][nr]   = z.x;
        tile[2*tx+1][nr] = z.y;
    }
    __syncthreads();
    #pragma unroll
    for (int r = 0; r < 8; r++) {
        int lr = ty + 8*r;
        size_t o = ((size_t)b*LL + (l0+lr)) * NV + n0 + tx;
        out[o] = x[o] + tile[lr][tx];
    }
}

// ---------------- launch ----------------
extern "C" void kernel_launch(void* const* d_in, const int* in_sizes, int n_in,
                              void* d_out, int out_size) {
    const float* x  = (const float*)d_in[0];
    const float* bb = (const float*)d_in[1];
    const float* W1 = (const float*)d_in[2];
    const float* b1 = (const float*)d_in[3];
    const float* W2 = (const float*)d_in[4];
    const float* b2 = (const float*)d_in[5];
    float* out = (float*)d_out;

    k_init<<<2, 1024>>>(bb);
    k_transpose<<<dim3(LL/64, NV/32, BB), dim3(32, 8)>>>(x);
    k_fft_fwd<<<NROWS, 256>>>();
    k_mag<<<dim3(9, BB, NG), 128>>>();
    k_magred<<<(BB*FF + 255)/256, 256>>>();
    k_gemm1<<<dim3((FF + 31)/32, NC), 256>>>(W1);
    k_gate2<<<BB, 256>>>(W2, b1, b2);
    k_inv<<<NROWS, 256>>>();
    k_addT<<<dim3(LL/64, NV/32, BB), dim3(32, 8)>>>(x, out);
}

// round 17
// speedup vs baseline: 1.0480x; 1.0480x over previous
#include <cuda_runtime.h>
#include <cuda_fp16.h>
#include <math.h>

#define BB 64
#define LL 4096
#define NV 128
#define FF 2049
#define MM 2048
#define NROWS (BB*NV)   // 8192
#define NG 8            // n-groups for mag partials (16 rows each)
#define NC 17           // split-K chunks for gemm1 (128 k each)
#define KB 9            // k-chunks for gate2a/b (256 k each)

// pad every 8 elements: conflict-free exchanges for the radix-8 Stockham
#define PD8(i) ((i) + ((i) >> 3))
#define SH2 2304   // PD8(2047)=2302

// ---------------- device scratch (static, no allocation) ----------------
static __device__ __half  d_xT[(size_t)NROWS * LL];     // 64MB: xT (fp16), later reused as rec
static __device__ __half2 d_Zh[(size_t)NROWS * MM];     // 64MB packed fwd FFT, fp16 (re,im)
static __device__ float   d_mean[NROWS];
static __device__ float   d_sv[NROWS];
static __device__ float   d_mag[BB * FF];
static __device__ float   d_magp[(size_t)NG * BB * FF]; // unnormalized mag partials
static __device__ float   d_hpart[(size_t)NC * BB * FF];
static __device__ float   d_lpart[KB * BB * 8];         // partial logits
static __device__ float   d_wmask[BB * FF];
static __device__ int     d_bandof[FF];
static __device__ float2  d_twf[2048];                  // e^{-2pi i j/2048}, full period
static __device__ float2  d_tw4096[1025];               // e^{-2pi i k/4096}

__device__ __forceinline__ float2 cmulf(float2 a, float2 b) {
    return make_float2(a.x*b.x - a.y*b.y, a.x*b.y + a.y*b.x);
}
__device__ __forceinline__ float2 cadd(float2 a, float2 b){ return make_float2(a.x+b.x, a.y+b.y); }
__device__ __forceinline__ float2 csub(float2 a, float2 b){ return make_float2(a.x-b.x, a.y-b.y); }
// SIGN<0: -i*d ; SIGN>0: +i*d
template<int SIGN> __device__ __forceinline__ float2 crot(float2 d){
    return (SIGN < 0) ? make_float2(d.y, -d.x) : make_float2(-d.y, d.x);
}

template<int SIGN> __device__ __forceinline__ void bfly4(float2 v[4]){
    float2 p = cadd(v[0], v[2]), q = csub(v[0], v[2]);
    float2 s = cadd(v[1], v[3]), d = csub(v[1], v[3]);
    float2 rd = crot<SIGN>(d);
    v[0] = cadd(p, s); v[2] = csub(p, s);
    v[1] = cadd(q, rd); v[3] = csub(q, rd);
}

template<int SIGN> __device__ __forceinline__ void bfly8(float2 v[8]){
    const float C = 0.70710678118654752f;
    float2 a0 = cadd(v[0], v[4]), b0 = csub(v[0], v[4]);
    float2 a1 = cadd(v[1], v[5]), b1 = csub(v[1], v[5]);
    float2 a2 = cadd(v[2], v[6]), b2 = csub(v[2], v[6]);
    float2 a3 = cadd(v[3], v[7]), b3 = csub(v[3], v[7]);
    // odd-part twiddles: w^1, w^2, w^3 with w = e^{SIGN*2pi i/8}
    float2 c1 = (SIGN < 0) ? make_float2(C*(b1.x + b1.y), C*(b1.y - b1.x))
                           : make_float2(C*(b1.x - b1.y), C*(b1.y + b1.x));
    float2 c2 = crot<SIGN>(b2);
    float2 c3 = (SIGN < 0) ? make_float2(C*(b3.y - b3.x), -C*(b3.x + b3.y))
                           : make_float2(-C*(b3.x + b3.y), C*(b3.x - b3.y));
    float2 e[4] = {a0, a1, a2, a3};  bfly4<SIGN>(e);
    float2 o[4] = {b0, c1, c2, c3};  bfly4<SIGN>(o);
    v[0]=e[0]; v[2]=e[1]; v[4]=e[2]; v[6]=e[3];
    v[1]=o[0]; v[3]=o[1]; v[5]=o[2]; v[7]=o[3];
}

__device__ __forceinline__ void twchain8(float2 v[8], float2 w1){
    float2 w = w1;
    v[1] = cmulf(v[1], w);
    #pragma unroll
    for (int r = 2; r < 8; r++) { w = cmulf(w, w1); v[r] = cmulf(v[r], w); }
}

__device__ __forceinline__ __half2 pack_h2(float2 a){ return __floats2half2_rn(a.x, a.y); }
__device__ __forceinline__ float2  unpk_h2(__half2 h){ return __half22float2(h); }

// 3 radix-8 Stockham passes (P=1,8,64), ping-pong HA->HB->HA through fp16
// shared (butterfly math stays fp32 in registers). Only 3 barriers.
// Result (sub-length-512 state) is left in HA; caller runs the final radix-4
// (P=512) pass fused with the global store.
template<int SIGN>
__device__ __forceinline__ void fft3pass(float2 v[8], __half2* HA, __half2* HB, int t){
    // pass 1: P=1 (no twiddle), out[8t + r] -> HA
    bfly8<SIGN>(v);
    #pragma unroll
    for (int r = 0; r < 8; r++) HA[PD8(8*t + r)] = pack_h2(v[r]);
    __syncthreads();
    // pass 2: P=8, HA -> HB
    #pragma unroll
    for (int r = 0; r < 8; r++) v[r] = unpk_h2(HA[PD8(t + 256*r)]);
    {
        int k = t & 7;
        float2 w1 = d_twf[k * 32]; if (SIGN > 0) w1.y = -w1.y;
        twchain8(v, w1);
        bfly8<SIGN>(v);
        int base = 8*(t - k) + k;
        #pragma unroll
        for (int r = 0; r < 8; r++) HB[PD8(base + 8*r)] = pack_h2(v[r]);
    }
    __syncthreads();
    // pass 3: P=64, HB -> HA
    #pragma unroll
    for (int r = 0; r < 8; r++) v[r] = unpk_h2(HB[PD8(t + 256*r)]);
    {
        int k = t & 63;
        float2 w1 = d_twf[k * 4]; if (SIGN > 0) w1.y = -w1.y;
        twchain8(v, w1);
        bfly8<SIGN>(v);
        int base = 8*(t - k) + k;
        #pragma unroll
        for (int r = 0; r < 8; r++) HA[PD8(base + 64*r)] = pack_h2(v[r]);
    }
    __syncthreads();
}

// ---------------- init: twiddles + band boundaries (one kernel) ----------------
__global__ void k_init(const float* __restrict__ bb) {
    int i = blockIdx.x * blockDim.x + threadIdx.x;
    if (i < 2048) {
        float s, c; sincospif(-(float)i / 1024.0f, &s, &c);
        d_twf[i] = make_float2(c, s);
    }
    if (i < 1025) {
        float s, c; sincospif(-(float)i / 2048.0f, &s, &c);
        d_tw4096[i] = make_float2(c, s);
    }
    if (blockIdx.x == 1 && threadIdx.x == 1023) {   // one thread, parallel with twiddle fill
        float s[7];
        for (int q = 0; q < 7; q++) s[q] = bb[q];
        for (int q = 1; q < 7; q++) {
            float v = s[q]; int j = q - 1;
            while (j >= 0 && s[j] > v) { s[j+1] = s[j]; j--; }
            s[j+1] = v;
        }
        float b01[9];
        b01[0] = 0.0f;
        for (int q = 0; q < 7; q++) b01[q+1] = 1.0f / (1.0f + expf(-s[q]));
        b01[8] = 1.0f;
        int idx[9];
        for (int q = 0; q < 9; q++) {
            int v = (int)(b01[q] * (float)FF);
            if (v < 0) v = 0; if (v > FF) v = FF;
            idx[q] = v;
        }
        idx[8] = FF;
        for (int e = 0; e < 8; e++)
            for (int f = idx[e]; f < idx[e+1]; f++) d_bandof[f] = e;
    }
}

// ---------------- transpose x[B,L,N] (fp32) -> xT[B,N,L] (fp16) ----------------
// tile: 64 l x 32 n. Loads 128B/warp fp32; stores 128B/warp half2.
__global__ __launch_bounds__(256) void k_transpose(const float* __restrict__ x) {
    __shared__ float tile[64][33];
    int b = blockIdx.z;
    int l0 = blockIdx.x * 64, n0 = blockIdx.y * 32;
    int tx = threadIdx.x, ty = threadIdx.y;
    #pragma unroll
    for (int r = 0; r < 8; r++) {
        int lr = ty + 8*r;
        tile[lr][tx] = x[((size_t)b*LL + (l0+lr)) * NV + n0 + tx];
    }
    __syncthreads();
    __half2* xo = (__half2*)d_xT;
    #pragma unroll
    for (int r = 0; r < 4; r++) {
        int nr = ty + 8*r;
        size_t o = ((size_t)b*NV + (n0+nr)) * (LL/2) + (l0/2) + tx;
        xo[o] = __floats2half2_rn(tile[2*tx][nr], tile[2*tx+1][nr]);
    }
}

// ---------------- forward FFT + row stats; store packed Z as fp16 ----------------
__global__ __launch_bounds__(256, 6) void k_fft_fwd() {
    __shared__ __half2 HA[SH2], HB[SH2];
    __shared__ float red[16];
    int t = threadIdx.x, row = blockIdx.x;
    int lane = t & 31, warp = t >> 5;
    const __half2* xr = (const __half2*)(d_xT + (size_t)row * LL);
    float2 v[8];
    float s1 = 0.f, s2 = 0.f;
    #pragma unroll
    for (int q = 0; q < 8; q++) {
        float2 z = __half22float2(xr[t + 256*q]);   // (x[2m], x[2m+1]) packing for free
        v[q] = z;
        s1 += z.x + z.y;
        s2 += z.x*z.x + z.y*z.y;
    }
    #pragma unroll
    for (int o = 16; o > 0; o >>= 1) {
        s1 += __shfl_xor_sync(0xffffffffu, s1, o);
        s2 += __shfl_xor_sync(0xffffffffu, s2, o);
    }
    if (lane == 0) { red[warp] = s1; red[warp + 8] = s2; }
    __syncthreads();
    if (t == 0) {
        float t1 = 0.f, t2 = 0.f;
        #pragma unroll
        for (int w = 0; w < 8; w++) { t1 += red[w]; t2 += red[w + 8]; }
        float mean = t1 * (1.0f / LL);
        float var  = t2 * (1.0f / LL) - mean*mean + 1e-6f;
        d_mean[row] = mean;
        d_sv[row]   = sqrtf(var);
    }
    // no extra sync needed: fft3pass writes HA/HB (disjoint from red); its first barrier covers it
    fft3pass<-1>(v, HA, HB, t);
    // final radix-4 pass (P=512) fused with fp16 global store
    __half2* Zr = d_Zh + (size_t)row * MM;
    #pragma unroll
    for (int h = 0; h < 2; h++) {
        int jj = t + 256*h;
        float2 u[4];
        #pragma unroll
        for (int m = 0; m < 4; m++) u[m] = unpk_h2(HA[PD8(jj + 512*m)]);
        float2 w1 = d_twf[jj];
        float2 w = w1;
        u[1] = cmulf(u[1], w); w = cmulf(w, w1); u[2] = cmulf(u[2], w); w = cmulf(w, w1); u[3] = cmulf(u[3], w);
        bfly4<-1>(u);
        #pragma unroll
        for (int m = 0; m < 4; m++)
            Zr[jj + 512*m] = pack_h2(u[m]);
    }
}

// ---------------- magp[g][b][f] = sum over 16-row n-group of |X[b,n,f]| ----------------
// dual accumulator chains (even/odd n) to double memory-level parallelism
__global__ __launch_bounds__(128) void k_mag() {
    int b = blockIdx.y;
    int g = blockIdx.z;
    int k = blockIdx.x * 128 + threadIdx.x;
    if (k > 1024) return;
    const __half2* Zb = d_Zh + (size_t)b * NV * MM + (size_t)(g * 16) * MM;
    float2 W = d_tw4096[k];
    float a1 = 0.f, a2 = 0.f;   // even-n chain
    float c1 = 0.f, c2 = 0.f;   // odd-n chain
    if (k == 0) {
        #pragma unroll 4
        for (int n = 0; n < 16; n += 2) {
            float2 z0 = __half22float2(Zb[(size_t)n * MM]);
            float2 z1 = __half22float2(Zb[(size_t)(n+1) * MM]);
            a1 += fabsf(z0.x + z0.y);  a2 += fabsf(z0.x - z0.y);
            c1 += fabsf(z1.x + z1.y);  c2 += fabsf(z1.x - z1.y);
        }
    } else if (k == 1024) {
        #pragma unroll 4
        for (int n = 0; n < 16; n += 2) {
            float2 z0 = __half22float2(Zb[(size_t)n * MM + 1024]);
            float2 z1 = __half22float2(Zb[(size_t)(n+1) * MM + 1024]);
            a1 += sqrtf(z0.x*z0.x + z0.y*z0.y);
            c1 += sqrtf(z1.x*z1.x + z1.y*z1.y);
        }
    } else {
        #pragma unroll 2
        for (int n = 0; n < 16; n += 2) {
            const __half2* Zr0 = Zb + (size_t)n * MM;
            const __half2* Zr1 = Zb + (size_t)(n+1) * MM;
            float2 zk0 = __half22float2(Zr0[k]);
            float2 zm0 = __half22float2(Zr0[MM - k]);
            float2 zk1 = __half22float2(Zr1[k]);
            float2 zm1 = __half22float2(Zr1[MM - k]);
            {
                float2 Xe = make_float2(0.5f*(zk0.x + zm0.x), 0.5f*(zk0.y - zm0.y));
                float2 T  = make_float2(zk0.x - zm0.x, zk0.y + zm0.y);
                float2 Xo = make_float2(0.5f*T.y, -0.5f*T.x);
                float2 WX = cmulf(W, Xo);
                float2 Xk = make_float2(Xe.x + WX.x, Xe.y + WX.y);
                float2 Xm = make_float2(Xe.x - WX.x, Xe.y - WX.y);
                a1 += sqrtf(Xk.x*Xk.x + Xk.y*Xk.y);
                a2 += sqrtf(Xm.x*Xm.x + Xm.y*Xm.y);
            }
            {
                float2 Xe = make_float2(0.5f*(zk1.x + zm1.x), 0.5f*(zk1.y - zm1.y));
                float2 T  = make_float2(zk1.x - zm1.x, zk1.y + zm1.y);
                float2 Xo = make_float2(0.5f*T.y, -0.5f*T.x);
                float2 WX = cmulf(W, Xo);
                float2 Xk = make_float2(Xe.x + WX.x, Xe.y + WX.y);
                float2 Xm = make_float2(Xe.x - WX.x, Xe.y - WX.y);
                c1 += sqrtf(Xk.x*Xk.x + Xk.y*Xk.y);
                c2 += sqrtf(Xm.x*Xm.x + Xm.y*Xm.y);
            }
        }
    }
    a1 += c1; a2 += c2;
    float* mp = d_magp + (size_t)g * BB * FF + b*FF;
    mp[k] = a1;
    if (k == 0)          mp[2048]   = a2;
    else if (k < 1024)   mp[MM - k] = a2;
}

// ---------------- mag[b][f] = (sum_g magp[g][b][f]) / NV ----------------
__global__ __launch_bounds__(256) void k_magred() {
    int idx = blockIdx.x * 256 + threadIdx.x;
    if (idx >= BB * FF) return;
    float s = 0.f;
    #pragma unroll
    for (int g = 0; g < NG; g++) s += d_magp[(size_t)g * BB * FF + idx];
    d_mag[idx] = s * (1.0f / NV);
}

// ---------------- GEMM1 split-K partials: hpart[c] = mag @ W1 (k chunk c, 128 wide) ----------------
__global__ __launch_bounds__(256) void k_gemm1(const float* __restrict__ W1) {
    __shared__ float Smag[16][65];   // [kk][b]
    __shared__ float Sw[16][33];     // [kk][j]
    int j0 = blockIdx.x * 32;
    int k0 = blockIdx.y * 128;
    int t = threadIdx.x;
    int bq = t >> 4;
    int jq = t & 15;
    float acc[4][2];
    #pragma unroll
    for (int i = 0; i < 4; i++) { acc[i][0] = 0.f; acc[i][1] = 0.f; }

    for (int ks = 0; ks < 128; ks += 16) {
        #pragma unroll
        for (int q = 0; q < 4; q++) {
            int e = t + 256*q;
            int bb2 = e >> 4, kk = e & 15;
            int kg = k0 + ks + kk;
            Smag[kk][bb2] = (kg < FF) ? d_mag[bb2*FF + kg] : 0.f;
        }
        #pragma unroll
        for (int q = 0; q < 2; q++) {
            int e = t + 256*q;
            int kk = e >> 5, j = e & 31;
            int kg = k0 + ks + kk, jg = j0 + j;
            Sw[kk][j] = (kg < FF && jg < FF) ? W1[(size_t)kg*FF + jg] : 0.f;
        }
        __syncthreads();
        #pragma unroll
        for (int kk = 0; kk < 16; kk++) {
            float m0 = Smag[kk][bq*4+0], m1 = Smag[kk][bq*4+1];
            float m2 = Smag[kk][bq*4+2], m3 = Smag[kk][bq*4+3];
            float w0 = Sw[kk][jq*2+0],   w1v = Sw[kk][jq*2+1];
            acc[0][0] += m0*w0; acc[0][1] += m0*w1v;
            acc[1][0] += m1*w0; acc[1][1] += m1*w1v;
            acc[2][0] += m2*w0; acc[2][1] += m2*w1v;
            acc[3][0] += m3*w0; acc[3][1] += m3*w1v;
        }
        __syncthreads();
    }
    float* hp = d_hpart + (size_t)blockIdx.y * BB * FF;
    #pragma unroll
    for (int i = 0; i < 4; i++) {
        int bb2 = bq*4 + i;
        #pragma unroll
        for (int jj = 0; jj < 2; jj++) {
            int jg = j0 + jq*2 + jj;
            if (jg < FF) hp[bb2*FF + jg] = acc[i][jj];
        }
    }
}

// ---------------- gate2a: partial logits per (k-chunk, batch) ----------------
// lpart[kc][b][e] = sum_{k in chunk} relu(b1[k] + sum_c hpart[c][b][k]) * W2[k][e]
__global__ __launch_bounds__(256) void k_gate2a(const float* __restrict__ W2,
                                                const float* __restrict__ b1) {
    __shared__ float sred[8][8];   // [warp][e]
    int kc = blockIdx.x, b = blockIdx.y;
    int t = threadIdx.x;
    int warp = t >> 5, lane = t & 31;
    int k = kc * 256 + t;
    float acc[8];
    #pragma unroll
    for (int e = 0; e < 8; e++) acc[e] = 0.f;
    if (k < FF) {
        float hv = b1[k];
        #pragma unroll
        for (int c = 0; c < NC; c++) hv += d_hpart[(size_t)c * BB * FF + b*FF + k];
        hv = fmaxf(hv, 0.f);
        #pragma unroll
        for (int e = 0; e < 8; e++) acc[e] = hv * W2[k*8 + e];
    }
    #pragma unroll
    for (int e = 0; e < 8; e++)
        #pragma unroll
        for (int o = 16; o > 0; o >>= 1)
            acc[e] += __shfl_xor_sync(0xffffffffu, acc[e], o);
    if (lane == 0)
        #pragma unroll
        for (int e = 0; e < 8; e++) sred[warp][e] = acc[e];
    __syncthreads();
    if (t < 8) {
        float s = 0.f;
        #pragma unroll
        for (int w = 0; w < 8; w++) s += sred[w][t];
        d_lpart[(kc * BB + b) * 8 + t] = s;
    }
}

// ---------------- gate2b: finish logits + softmax (redundant per CTA), fill wmask chunk ----------------
__global__ __launch_bounds__(256) void k_gate2b(const float* __restrict__ b2) {
    __shared__ float sw[8];
    __shared__ float slog[8];
    int kc = blockIdx.x, b = blockIdx.y;
    int t = threadIdx.x;
    if (t < 8) {
        float s = b2[t];
        #pragma unroll
        for (int c = 0; c < KB; c++) s += d_lpart[(c * BB + b) * 8 + t];
        slog[t] = s;
    }
    __syncthreads();
    if (t == 0) {
        float mx = slog[0];
        for (int e = 1; e < 8; e++) mx = fmaxf(mx, slog[e]);
        float den = 0.f, ex[8];
        for (int e = 0; e < 8; e++) { ex[e] = expf(slog[e] - mx); den += ex[e]; }
        for (int e = 0; e < 8; e++) sw[e] = ex[e] / den;
    }
    __syncthreads();
    int f = kc * 256 + t;
    if (f < FF) d_wmask[b*FF + f] = sw[d_bandof[f]];
}

// ---------------- inverse: masked unpack from fp16 Z (global), irfft, rescale; fp16 rec ----------------
__global__ __launch_bounds__(256, 6) void k_inv() {
    __shared__ __half2 HA[SH2], HB[SH2];
    int t = threadIdx.x, row = blockIdx.x;
    int b = row >> 7;               // row / NV
    const __half2* Zr = d_Zh + (size_t)row * MM;
    const float*   wm = d_wmask + b*FF;

    // masked Hermitian unpack straight from global fp16 Z into inverse pass-1 registers.
    // Both j and MM-j sides are contiguous per warp; the mirrored second touch is an L2 hit.
    float2 v[8];
    #pragma unroll
    for (int r = 0; r < 8; r++) {
        int j = t + 256*r;
        if (j == 0) {
            float2 z = __half22float2(Zr[0]);
            float Y0 = wm[0]    * (z.x + z.y);
            float Y2 = wm[2048] * (z.x - z.y);
            v[r] = make_float2(0.5f*(Y0 + Y2), 0.5f*(Y0 - Y2));
        } else if (j == 1024) {
            float m = wm[1024];
            float2 z = __half22float2(Zr[1024]);
            v[r] = make_float2(m*z.x, m*z.y);
        } else {
            int jl = (j < 1024) ? j : (2048 - j);
            float2 a  = __half22float2(Zr[jl]);
            float2 bz = __half22float2(Zr[2048 - jl]);
            float2 E  = make_float2(0.5f*(a.x + bz.x), 0.5f*(a.y - bz.y));
            float2 Tp = make_float2(a.x - bz.x, a.y + bz.y);
            float2 O  = make_float2(0.5f*Tp.y, -0.5f*Tp.x);
            float2 Wj = d_tw4096[jl];
            float2 T  = cmulf(Wj, O);
            float mj = wm[jl], mm2 = wm[2048 - jl];
            float p = 0.5f*(mj + mm2), qv = 0.5f*(mj - mm2);
            float2 Ep = make_float2(p*E.x + qv*T.x, p*E.y + qv*T.y);
            float2 Ot = make_float2(qv*E.x + p*T.x, qv*E.y + p*T.y);
            float2 Wc = make_float2(Wj.x, -Wj.y);
            float2 Op = cmulf(Wc, Ot);
            v[r] = (j < 1024) ? make_float2(Ep.x - Op.y,  Ep.y + Op.x)
                              : make_float2(Ep.x + Op.y, -Ep.y + Op.x);
        }
    }

    fft3pass<+1>(v, HA, HB, t);

    float sv = d_sv[row] * (1.0f / MM);
    float mean = d_mean[row];
    __half2* rec = (__half2*)(d_xT + (size_t)row * LL);
    #pragma unroll
    for (int h = 0; h < 2; h++) {
        int jj = t + 256*h;
        float2 u[4];
        #pragma unroll
        for (int m = 0; m < 4; m++) u[m] = unpk_h2(HA[PD8(jj + 512*m)]);
        float2 w1 = d_twf[jj]; w1.y = -w1.y;   // SIGN=+1
        float2 w = w1;
        u[1] = cmulf(u[1], w); w = cmulf(w, w1); u[2] = cmulf(u[2], w); w = cmulf(w, w1); u[3] = cmulf(u[3], w);
        bfly4<+1>(u);
        #pragma unroll
        for (int m = 0; m < 4; m++)
            rec[jj + 512*m] = __floats2half2_rn(u[m].x*sv + mean, u[m].y*sv + mean);
    }
}

// ---------------- out[b,l,n] = x[b,l,n] + rec[b,n,l] (rec fp16) ----------------
// tile: 64 l x 32 n. Loads 128B/warp half2; stores/loads 128B/warp fp32.
__global__ __launch_bounds__(256) void k_addT(const float* __restrict__ x,
                                              float* __restrict__ out) {
    __shared__ float tile[64][33];
    int b = blockIdx.z;
    int l0 = blockIdx.x * 64, n0 = blockIdx.y * 32;
    int tx = threadIdx.x, ty = threadIdx.y;
    const __half2* ri = (const __half2*)d_xT;
    #pragma unroll
    for (int r = 0; r < 4; r++) {
        int nr = ty + 8*r;
        size_t o = ((size_t)b*NV + (n0+nr)) * (LL/2) + (l0/2) + tx;
        float2 z = __half22float2(ri[o]);
        tile[2*tx][nr]   = z.x;
        tile[2*tx+1][nr] = z.y;
    }
    __syncthreads();
    #pragma unroll
    for (int r = 0; r < 8; r++) {
        int lr = ty + 8*r;
        size_t o = ((size_t)b*LL + (l0+lr)) * NV + n0 + tx;
        out[o] = x[o] + tile[lr][tx];
    }
}

// ---------------- launch ----------------
extern "C" void kernel_launch(void* const* d_in, const int* in_sizes, int n_in,
                              void* d_out, int out_size) {
    const float* x  = (const float*)d_in[0];
    const float* bb = (const float*)d_in[1];
    const float* W1 = (const float*)d_in[2];
    const float* b1 = (const float*)d_in[3];
    const float* W2 = (const float*)d_in[4];
    const float* b2 = (const float*)d_in[5];
    float* out = (float*)d_out;

    k_init<<<2, 1024>>>(bb);
    k_transpose<<<dim3(LL/64, NV/32, BB), dim3(32, 8)>>>(x);
    k_fft_fwd<<<NROWS, 256>>>();
    k_mag<<<dim3(9, BB, NG), 128>>>();
    k_magred<<<(BB*FF + 255)/256, 256>>>();
    k_gemm1<<<dim3((FF + 31)/32, NC), 256>>>(W1);
    k_gate2a<<<dim3(KB, BB), 256>>>(W2, b1);
    k_gate2b<<<dim3(KB, BB), 256>>>(b2);
    k_inv<<<NROWS, 256>>>();
    k_addT<<<dim3(LL/64, NV/32, BB), dim3(32, 8)>>>(x, out);
}